// round 14
// baseline (speedup 1.0000x reference)
#include <cuda_runtime.h>
#include <cstdint>

#define Hh   181
#define KK   92           // k-pairs: covers k=0..183 (zeros beyond 180)
#define KKP  (KK + 1)     // +1 pad row so distance-1 prefetch never branches
#define Tt   1024
#define ROWS 8
#define NBLK 128
#define NTHR 192

// Packed pair weights: [kk*Hh + j]
//   g_wA = (wr[2kk], wr[2kk+1], wz[2kk], wz[2kk+1])
//   g_wN = (wn[2kk], wn[2kk+1])
__device__ __align__(16) float4 g_wA[KKP * Hh];   // pad row stays zero
__device__ __align__(16) float2 g_wN[KKP * Hh];

// packed f32x2 FMA: acc = a*b + acc (two independent fp32 lanes)
#define FMA2(acc, a, b) \
    asm("fma.rn.f32x2 %0, %1, %2, %0;" : "+l"(acc) : "l"(a), "l"(b))

__device__ __forceinline__ float hsum2(unsigned long long v) {
    float lo = __uint_as_float((unsigned)(v & 0xFFFFFFFFull));
    float hi = __uint_as_float((unsigned)(v >> 32));
    return lo + hi;
}

__global__ void prep_w_kernel(const float* __restrict__ w_hh) {
    int idx = blockIdx.x * blockDim.x + threadIdx.x;
    if (idx >= KK * Hh) return;
    int kk = idx / Hh, j = idx % Hh;
    int k0 = 2 * kk, k1 = 2 * kk + 1;
    float r0 = w_hh[j * Hh + k0];
    float r1 = (k1 < Hh) ? w_hh[j * Hh + k1] : 0.f;
    float z0 = w_hh[(Hh + j) * Hh + k0];
    float z1 = (k1 < Hh) ? w_hh[(Hh + j) * Hh + k1] : 0.f;
    float n0 = w_hh[(2 * Hh + j) * Hh + k0];
    float n1 = (k1 < Hh) ? w_hh[(2 * Hh + j) * Hh + k1] : 0.f;
    if (k0 >= Hh) { r0 = z0 = n0 = 0.f; }
    g_wA[idx] = make_float4(r0, r1, z0, z1);
    g_wN[idx] = make_float2(n0, n1);
}

__global__ __launch_bounds__(NTHR, 1) void gru_kernel(
    const float* __restrict__ x,
    const float* __restrict__ w_ih,
    const float* __restrict__ b_ih,
    const float* __restrict__ b_hh,
    const float* __restrict__ w_fc,
    const float* __restrict__ b_fc,
    float* __restrict__ out)
{
    __shared__ __align__(16) float xs[Tt][ROWS];           // 32 KB
    __shared__ __align__(16) float2 hT2[2][KK][ROWS];      // 11.5 KB double-buffered

    const int tid = threadIdx.x;
    const int blk = blockIdx.x;

    for (int i = tid; i < ROWS * Tt; i += NTHR) {
        int r = i / Tt, t = i % Tt;
        xs[t][r] = x[(blk * ROWS + r) * Tt + t];
    }
    for (int i = tid; i < 2 * KK * ROWS * 2; i += NTHR)
        ((float*)hT2)[i] = 0.f;

    // One thread per gate j, handling ALL 8 rows (24 FMA2 per 24B of weights).
    const int  j   = tid;
    const bool act = (j < Hh);
    const int  jj  = act ? j : 0;

    float wihR = 0.f, wihZ = 0.f, wihN = 0.f;
    float bR = 0.f, bZ = 0.f, bihN = 0.f, bhhN = 0.f;
    if (act) {
        wihR = w_ih[j]; wihZ = w_ih[Hh + j]; wihN = w_ih[2 * Hh + j];
        bR   = b_ih[j]          + b_hh[j];
        bZ   = b_ih[Hh + j]     + b_hh[Hh + j];
        bihN = b_ih[2 * Hh + j];
        bhhN = b_hh[2 * Hh + j];
    }
    float hprev[ROWS];
    #pragma unroll
    for (int r = 0; r < ROWS; ++r) hprev[r] = 0.f;

    __syncthreads();

    int cur = 0;
    #pragma unroll 1
    for (int t = 0; t < Tt; ++t) {
        unsigned long long aR[ROWS] = {0,0,0,0,0,0,0,0};
        unsigned long long aZ[ROWS] = {0,0,0,0,0,0,0,0};
        unsigned long long aN[ROWS] = {0,0,0,0,0,0,0,0};

        // Distance-1 prefetch (pad row makes kk+1 always loadable).
        ulonglong2 w1 = *(const ulonglong2*)&g_wA[jj];
        unsigned long long wn2 = *(const unsigned long long*)&g_wN[jj];

        const float2 (*hb)[ROWS] = hT2[cur];
        #pragma unroll 2
        for (int kk = 0; kk < KK; ++kk) {
            ulonglong2 w1n = *(const ulonglong2*)&g_wA[(kk + 1) * Hh + jj];
            unsigned long long wn2n = *(const unsigned long long*)&g_wN[(kk + 1) * Hh + jj];
            const ulonglong2* hp = (const ulonglong2*)&hb[kk][0];
            ulonglong2 h01 = hp[0];   // rows 0,1 (each ull = k-pair for one row)
            ulonglong2 h23 = hp[1];
            ulonglong2 h45 = hp[2];
            ulonglong2 h67 = hp[3];
            FMA2(aR[0], w1.x, h01.x); FMA2(aR[1], w1.x, h01.y);
            FMA2(aR[2], w1.x, h23.x); FMA2(aR[3], w1.x, h23.y);
            FMA2(aR[4], w1.x, h45.x); FMA2(aR[5], w1.x, h45.y);
            FMA2(aR[6], w1.x, h67.x); FMA2(aR[7], w1.x, h67.y);
            FMA2(aZ[0], w1.y, h01.x); FMA2(aZ[1], w1.y, h01.y);
            FMA2(aZ[2], w1.y, h23.x); FMA2(aZ[3], w1.y, h23.y);
            FMA2(aZ[4], w1.y, h45.x); FMA2(aZ[5], w1.y, h45.y);
            FMA2(aZ[6], w1.y, h67.x); FMA2(aZ[7], w1.y, h67.y);
            FMA2(aN[0], wn2,  h01.x); FMA2(aN[1], wn2,  h01.y);
            FMA2(aN[2], wn2,  h23.x); FMA2(aN[3], wn2,  h23.y);
            FMA2(aN[4], wn2,  h45.x); FMA2(aN[5], wn2,  h45.y);
            FMA2(aN[6], wn2,  h67.x); FMA2(aN[7], wn2,  h67.y);
            w1 = w1n; wn2 = wn2n;
        }

        // Epilogue on thread-local accumulators; write the OTHER buffer
        // (no WAR hazard) -> ONE barrier per step.
        if (act) {
            float4 xv0 = *(const float4*)&xs[t][0];
            float4 xv1 = *(const float4*)&xs[t][4];
            float xr[ROWS] = {xv0.x, xv0.y, xv0.z, xv0.w,
                              xv1.x, xv1.y, xv1.z, xv1.w};
            float hn[ROWS];
            #pragma unroll
            for (int r = 0; r < ROWS; ++r) {
                float pr = hsum2(aR[r]) + xr[r] * wihR + bR;
                float rg = __fdividef(1.f, 1.f + __expf(-pr));
                float pz = hsum2(aZ[r]) + xr[r] * wihZ + bZ;
                float zg = __fdividef(1.f, 1.f + __expf(-pz));
                float pn = xr[r] * wihN + bihN + rg * (hsum2(aN[r]) + bhhN);
                float e2 = __expf(-2.f * fabsf(pn));
                float th = copysignf(__fdividef(1.f - e2, 1.f + e2), pn);
                hn[r] = (1.f - zg) * th + zg * hprev[r];
                hprev[r] = hn[r];
            }
            // scatter into pair layout: component (j&1) of hT2[j>>1][row]
            float* hw = (float*)hT2[cur ^ 1] + (j >> 1) * (ROWS * 2) + (j & 1);
            #pragma unroll
            for (int r = 0; r < ROWS; ++r)
                hw[r * 2] = hn[r];
        }
        __syncthreads();   // h_new visible before next step
        cur ^= 1;
    }

    // After 1024 steps cur==0; final h lives in hT2[0].
    if (tid < ROWS * 10) {
        int r = tid / 10, c = tid % 10;
        float s = b_fc[c];
        const float* hb = (const float*)hT2[0];
        #pragma unroll 4
        for (int k = 0; k < Hh; ++k)
            s += hb[(k >> 1) * (ROWS * 2) + r * 2 + (k & 1)] * __ldg(&w_fc[c * Hh + k]);
        out[(blk * ROWS + r) * 10 + c] = s;
    }
}

extern "C" void kernel_launch(void* const* d_in, const int* in_sizes, int n_in,
                              void* d_out, int out_size) {
    const float* x    = (const float*)d_in[0];
    const float* w_ih = (const float*)d_in[1];
    const float* w_hh = (const float*)d_in[2];
    const float* b_ih = (const float*)d_in[3];
    const float* b_hh = (const float*)d_in[4];
    const float* w_fc = (const float*)d_in[5];
    const float* b_fc = (const float*)d_in[6];

    prep_w_kernel<<<(KK * Hh + 255) / 256, 256>>>(w_hh);
    gru_kernel<<<NBLK, NTHR>>>(x, w_ih, b_ih, b_hh, w_fc, b_fc, (float*)d_out);
}

// round 16
// speedup vs baseline: 1.0015x; 1.0015x over previous
#include <cuda_runtime.h>
#include <cstdint>

#define Hh   181
#define KK   92           // k-pairs: covers k=0..183 (zeros beyond 180)
#define KKP  (KK + 1)     // +1 pad row so distance-1 prefetch never branches
#define Tt   1024
#define ROWS 4
#define NBLK 256
#define NCMP 192          // compute threads (6 warps)
#define NTHR 224          // + 1 loader warp
#define SEG  23           // progress granularity in kk units (4 segs/step)
#define LEAD 30           // loader may run <= LEAD kk ahead of compute

// Packed pair weights: [kk*Hh + j]
__device__ __align__(16) float4 g_wA[KKP * Hh];   // pad row stays zero
__device__ __align__(16) float2 g_wN[KKP * Hh];

#define FMA2(acc, a, b) \
    asm("fma.rn.f32x2 %0, %1, %2, %0;" : "+l"(acc) : "l"(a), "l"(b))

__device__ __forceinline__ float hsum2(unsigned long long v) {
    float lo = __uint_as_float((unsigned)(v & 0xFFFFFFFFull));
    float hi = __uint_as_float((unsigned)(v >> 32));
    return lo + hi;
}

__global__ void prep_w_kernel(const float* __restrict__ w_hh) {
    int idx = blockIdx.x * blockDim.x + threadIdx.x;
    if (idx >= KK * Hh) return;
    int kk = idx / Hh, j = idx % Hh;
    int k0 = 2 * kk, k1 = 2 * kk + 1;
    float r0 = w_hh[j * Hh + k0];
    float r1 = (k1 < Hh) ? w_hh[j * Hh + k1] : 0.f;
    float z0 = w_hh[(Hh + j) * Hh + k0];
    float z1 = (k1 < Hh) ? w_hh[(Hh + j) * Hh + k1] : 0.f;
    float n0 = w_hh[(2 * Hh + j) * Hh + k0];
    float n1 = (k1 < Hh) ? w_hh[(2 * Hh + j) * Hh + k1] : 0.f;
    if (k0 >= Hh) { r0 = z0 = n0 = 0.f; }
    g_wA[idx] = make_float4(r0, r1, z0, z1);
    g_wN[idx] = make_float2(n0, n1);
}

__global__ __launch_bounds__(NTHR, 2) void gru_kernel(
    const float* __restrict__ x,
    const float* __restrict__ w_ih,
    const float* __restrict__ b_ih,
    const float* __restrict__ b_hh,
    const float* __restrict__ w_fc,
    const float* __restrict__ b_fc,
    float* __restrict__ out)
{
    __shared__ __align__(16) float xs[Tt][ROWS];           // 16 KB
    __shared__ __align__(16) float2 hT2[2][KK][ROWS];      // 5.75 KB double-buffered
    __shared__ volatile int sProg;                         // compute progress (linear kk)

    const int tid = threadIdx.x;
    const int blk = blockIdx.x;

    for (int i = tid; i < ROWS * Tt; i += NTHR) {
        int r = i / Tt, t = i % Tt;
        xs[t][r] = x[(blk * ROWS + r) * Tt + t];
    }
    for (int i = tid; i < 2 * KK * ROWS * 2; i += NTHR)
        ((float*)hT2)[i] = 0.f;
    if (tid == 0) sProg = -1;
    __syncthreads();          // only block-wide barrier (all 224 threads)

    if (tid >= NCMP) {
        // ---------------- loader warp: pure L1 prefetch hints ----------------
        const int lane = tid - NCMP;
        #pragma unroll 1
        for (int g = 0; g < Tt * 4; ++g) {
            const int target = g * SEG;          // linear kk where this chunk starts
            while (sProg < target - LEAD) __nanosleep(200);
            const int kk0 = (g & 3) * SEG;       // chunk within the step (weights repeat)
            const char* baseA = (const char*)&g_wA[kk0 * Hh];
            const char* baseN = (const char*)&g_wN[kk0 * Hh];
            const int spanA = SEG * Hh * 16;     // 66,608 B
            const int spanN = SEG * Hh * 8;      // 33,304 B
            for (int off = lane * 128; off < spanA; off += 32 * 128)
                asm volatile("prefetch.global.L1 [%0];" :: "l"(baseA + off));
            for (int off = lane * 128; off < spanN; off += 32 * 128)
                asm volatile("prefetch.global.L1 [%0];" :: "l"(baseN + off));
        }
        return;   // loader exits; never touches compute barriers
    }

    // ---------------- compute threads (R12 body, named barriers) ----------------
    const int  j   = tid;
    const bool act = (j < Hh);
    const int  jj  = act ? j : 0;

    float wihR = 0.f, wihZ = 0.f, wihN = 0.f;
    float bR = 0.f, bZ = 0.f, bihN = 0.f, bhhN = 0.f;
    if (act) {
        wihR = w_ih[j]; wihZ = w_ih[Hh + j]; wihN = w_ih[2 * Hh + j];
        bR   = b_ih[j]          + b_hh[j];
        bZ   = b_ih[Hh + j]     + b_hh[Hh + j];
        bihN = b_ih[2 * Hh + j];
        bhhN = b_hh[2 * Hh + j];
    }
    float hprev[4] = {0.f, 0.f, 0.f, 0.f};

    int cur = 0;
    #pragma unroll 1
    for (int t = 0; t < Tt; ++t) {
        unsigned long long aR[4] = {0,0,0,0};
        unsigned long long aZ[4] = {0,0,0,0};
        unsigned long long aN[4] = {0,0,0,0};

        ulonglong2 w1 = *(const ulonglong2*)&g_wA[jj];
        unsigned long long wn2 = *(const unsigned long long*)&g_wN[jj];

        const float2 (*hb)[ROWS] = hT2[cur];
        #pragma unroll 4
        for (int kk = 0; kk < KK; ++kk) {
            // progress beacon for the loader (uniform branch; 1-in-4 unroll instances)
            if (kk == 0 || kk == 23 || kk == 46 || kk == 69) {
                if (tid == 0) sProg = t * KK + kk;
            }
            ulonglong2 w1n = *(const ulonglong2*)&g_wA[(kk + 1) * Hh + jj];
            unsigned long long wn2n = *(const unsigned long long*)&g_wN[(kk + 1) * Hh + jj];
            ulonglong2 hA = *(const ulonglong2*)&hb[kk][0];
            ulonglong2 hB = *(const ulonglong2*)&hb[kk][2];
            FMA2(aR[0], w1.x, hA.x); FMA2(aR[1], w1.x, hA.y);
            FMA2(aR[2], w1.x, hB.x); FMA2(aR[3], w1.x, hB.y);
            FMA2(aZ[0], w1.y, hA.x); FMA2(aZ[1], w1.y, hA.y);
            FMA2(aZ[2], w1.y, hB.x); FMA2(aZ[3], w1.y, hB.y);
            FMA2(aN[0], wn2,  hA.x); FMA2(aN[1], wn2,  hA.y);
            FMA2(aN[2], wn2,  hB.x); FMA2(aN[3], wn2,  hB.y);
            w1 = w1n; wn2 = wn2n;
        }

        if (act) {
            float4 xv = *(const float4*)&xs[t][0];
            float xr[4] = {xv.x, xv.y, xv.z, xv.w};
            float hn[4];
            #pragma unroll
            for (int r = 0; r < 4; ++r) {
                float pr = hsum2(aR[r]) + xr[r] * wihR + bR;
                float rg = __fdividef(1.f, 1.f + __expf(-pr));
                float pz = hsum2(aZ[r]) + xr[r] * wihZ + bZ;
                float zg = __fdividef(1.f, 1.f + __expf(-pz));
                float pn = xr[r] * wihN + bihN + rg * (hsum2(aN[r]) + bhhN);
                float e2 = __expf(-2.f * fabsf(pn));
                float th = copysignf(__fdividef(1.f - e2, 1.f + e2), pn);
                hn[r] = (1.f - zg) * th + zg * hprev[r];
                hprev[r] = hn[r];
            }
            float* hw = (float*)hT2[cur ^ 1] + (j >> 1) * (ROWS * 2) + (j & 1);
            hw[0 * 2] = hn[0];
            hw[1 * 2] = hn[1];
            hw[2 * 2] = hn[2];
            hw[3 * 2] = hn[3];
        }
        // named barrier: 6 compute warps only (loader excluded)
        asm volatile("bar.sync 1, %0;" :: "n"(NCMP) : "memory");
        cur ^= 1;
    }

    // After 1024 steps cur==0; final h lives in hT2[0].
    if (tid < ROWS * 10) {
        int r = tid / 10, c = tid % 10;
        float s = b_fc[c];
        const float* hb = (const float*)hT2[0];
        #pragma unroll 4
        for (int k = 0; k < Hh; ++k)
            s += hb[(k >> 1) * (ROWS * 2) + r * 2 + (k & 1)] * __ldg(&w_fc[c * Hh + k]);
        out[(blk * ROWS + r) * 10 + c] = s;
    }
}

extern "C" void kernel_launch(void* const* d_in, const int* in_sizes, int n_in,
                              void* d_out, int out_size) {
    const float* x    = (const float*)d_in[0];
    const float* w_ih = (const float*)d_in[1];
    const float* w_hh = (const float*)d_in[2];
    const float* b_ih = (const float*)d_in[3];
    const float* b_hh = (const float*)d_in[4];
    const float* w_fc = (const float*)d_in[5];
    const float* b_fc = (const float*)d_in[6];

    prep_w_kernel<<<(KK * Hh + 255) / 256, 256>>>(w_hh);
    gru_kernel<<<NBLK, NTHR>>>(x, w_ih, b_ih, b_hh, w_fc, b_fc, (float*)d_out);
}

// round 17
// speedup vs baseline: 1.5567x; 1.5544x over previous
#include <cuda_runtime.h>
#include <cstdint>

#define Hh   181
#define KK   92           // k-pairs: covers k=0..183 (zeros beyond 180)
#define KKP  (KK + 1)     // +1 pad row so distance-1 prefetch never branches
#define Tt   1024
#define ROWS 8
#define NBLK 128
#define NTHR 384

// Packed pair weights: [kk*Hh + j]
//   g_wA = (wr[2kk], wr[2kk+1], wz[2kk], wz[2kk+1])
//   g_wN = (wn[2kk], wn[2kk+1])
__device__ __align__(16) float4 g_wA[KKP * Hh];   // pad row stays zero
__device__ __align__(16) float2 g_wN[KKP * Hh];

// packed f32x2 FMA: acc = a*b + acc (two independent fp32 lanes)
#define FMA2(acc, a, b) \
    asm("fma.rn.f32x2 %0, %1, %2, %0;" : "+l"(acc) : "l"(a), "l"(b))

__device__ __forceinline__ float hsum2(unsigned long long v) {
    float lo = __uint_as_float((unsigned)(v & 0xFFFFFFFFull));
    float hi = __uint_as_float((unsigned)(v >> 32));
    return lo + hi;
}

__global__ void prep_w_kernel(const float* __restrict__ w_hh) {
    int idx = blockIdx.x * blockDim.x + threadIdx.x;
    if (idx >= KK * Hh) return;
    int kk = idx / Hh, j = idx % Hh;
    int k0 = 2 * kk, k1 = 2 * kk + 1;
    float r0 = w_hh[j * Hh + k0];
    float r1 = (k1 < Hh) ? w_hh[j * Hh + k1] : 0.f;
    float z0 = w_hh[(Hh + j) * Hh + k0];
    float z1 = (k1 < Hh) ? w_hh[(Hh + j) * Hh + k1] : 0.f;
    float n0 = w_hh[(2 * Hh + j) * Hh + k0];
    float n1 = (k1 < Hh) ? w_hh[(2 * Hh + j) * Hh + k1] : 0.f;
    if (k0 >= Hh) { r0 = z0 = n0 = 0.f; }
    g_wA[idx] = make_float4(r0, r1, z0, z1);
    g_wN[idx] = make_float2(n0, n1);
}

__global__ __launch_bounds__(NTHR, 1) void gru_kernel(
    const float* __restrict__ x,
    const float* __restrict__ w_ih,
    const float* __restrict__ b_ih,
    const float* __restrict__ b_hh,
    const float* __restrict__ w_fc,
    const float* __restrict__ b_fc,
    float* __restrict__ out)
{
    __shared__ __align__(16) float xs[Tt][ROWS];           // 32 KB
    __shared__ __align__(16) float2 hT2[2][KK][ROWS];      // 11.5 KB double-buffered

    const int tid = threadIdx.x;
    const int blk = blockIdx.x;

    // Stage x rows (coalesced in t); zero both h buffers.
    for (int i = tid; i < ROWS * Tt; i += NTHR) {
        int r = i / Tt, t = i % Tt;
        xs[t][r] = x[(blk * ROWS + r) * Tt + t];
    }
    for (int i = tid; i < 2 * KK * ROWS * 2; i += NTHR)
        ((float*)hT2)[i] = 0.f;

    // Thread pair (2j, 2j+1) shares gate j; even -> rows 0..3, odd -> rows 4..7.
    // Lane-sharing of j halves weight wavefronts (16 distinct j per warp).
    const int  j   = tid >> 1;
    const int  hi  = tid & 1;
    const bool act = (j < Hh);
    const int  jj  = act ? j : 0;
    const int  rb  = hi * 4;

    float wihR = 0.f, wihZ = 0.f, wihN = 0.f;
    float bR = 0.f, bZ = 0.f, bihN = 0.f, bhhN = 0.f;
    if (act) {
        wihR = w_ih[j]; wihZ = w_ih[Hh + j]; wihN = w_ih[2 * Hh + j];
        bR   = b_ih[j]          + b_hh[j];
        bZ   = b_ih[Hh + j]     + b_hh[Hh + j];
        bihN = b_ih[2 * Hh + j];
        bhhN = b_hh[2 * Hh + j];
    }
    float hprev[4] = {0.f, 0.f, 0.f, 0.f};

    __syncthreads();

    int cur = 0;
    #pragma unroll 1
    for (int t = 0; t < Tt; ++t) {
        unsigned long long aR[4] = {0,0,0,0};
        unsigned long long aZ[4] = {0,0,0,0};
        unsigned long long aN[4] = {0,0,0,0};

        // Distance-1 prefetch (pad row makes kk+1 always loadable).
        ulonglong2 w1 = *(const ulonglong2*)&g_wA[jj];
        unsigned long long wn2 = *(const unsigned long long*)&g_wN[jj];

        const float2 (*hb)[ROWS] = hT2[cur];
        #pragma unroll 4
        for (int kk = 0; kk < KK; ++kk) {
            ulonglong2 w1n = *(const ulonglong2*)&g_wA[(kk + 1) * Hh + jj];
            unsigned long long wn2n = *(const unsigned long long*)&g_wN[(kk + 1) * Hh + jj];
            ulonglong2 hA = *(const ulonglong2*)&hb[kk][rb];
            ulonglong2 hB = *(const ulonglong2*)&hb[kk][rb + 2];
            FMA2(aR[0], w1.x, hA.x); FMA2(aR[1], w1.x, hA.y);
            FMA2(aR[2], w1.x, hB.x); FMA2(aR[3], w1.x, hB.y);
            FMA2(aZ[0], w1.y, hA.x); FMA2(aZ[1], w1.y, hA.y);
            FMA2(aZ[2], w1.y, hB.x); FMA2(aZ[3], w1.y, hB.y);
            FMA2(aN[0], wn2,  hA.x); FMA2(aN[1], wn2,  hA.y);
            FMA2(aN[2], wn2,  hB.x); FMA2(aN[3], wn2,  hB.y);
            w1 = w1n; wn2 = wn2n;
        }

        // Epilogue on thread-local accumulators; write the OTHER buffer
        // (no WAR hazard) -> ONE barrier per step.
        if (act) {
            float4 xv = *(const float4*)&xs[t][rb];
            float xr[4] = {xv.x, xv.y, xv.z, xv.w};
            float hn[4];
            #pragma unroll
            for (int r = 0; r < 4; ++r) {
                float pr = hsum2(aR[r]) + xr[r] * wihR + bR;
                float rg = __fdividef(1.f, 1.f + __expf(-pr));
                float pz = hsum2(aZ[r]) + xr[r] * wihZ + bZ;
                float zg = __fdividef(1.f, 1.f + __expf(-pz));
                float pn = xr[r] * wihN + bihN + rg * (hsum2(aN[r]) + bhhN);
                float e2 = __expf(-2.f * fabsf(pn));
                float th = copysignf(__fdividef(1.f - e2, 1.f + e2), pn);
                hn[r] = (1.f - zg) * th + zg * hprev[r];
                hprev[r] = hn[r];
            }
            // scatter into pair layout: component (j&1) of hT2[cur^1][j>>1][row]
            float* hw = (float*)hT2[cur ^ 1] + (j >> 1) * (ROWS * 2) + (j & 1);
            hw[(rb + 0) * 2] = hn[0];
            hw[(rb + 1) * 2] = hn[1];
            hw[(rb + 2) * 2] = hn[2];
            hw[(rb + 3) * 2] = hn[3];
        }
        __syncthreads();   // single barrier: h_new visible before next step
        cur ^= 1;
    }

    // After 1024 steps (even), final h lives in hT2[0].
    if (tid < ROWS * 10) {
        int r = tid / 10, c = tid % 10;
        float s = b_fc[c];
        const float* hb = (const float*)hT2[0];
        #pragma unroll 4
        for (int k = 0; k < Hh; ++k)
            s += hb[(k >> 1) * (ROWS * 2) + r * 2 + (k & 1)] * __ldg(&w_fc[c * Hh + k]);
        out[(blk * ROWS + r) * 10 + c] = s;
    }
}

extern "C" void kernel_launch(void* const* d_in, const int* in_sizes, int n_in,
                              void* d_out, int out_size) {
    const float* x    = (const float*)d_in[0];
    const float* w_ih = (const float*)d_in[1];
    const float* w_hh = (const float*)d_in[2];
    const float* b_ih = (const float*)d_in[3];
    const float* b_hh = (const float*)d_in[4];
    const float* w_fc = (const float*)d_in[5];
    const float* b_fc = (const float*)d_in[6];

    prep_w_kernel<<<(KK * Hh + 255) / 256, 256>>>(w_hh);
    gru_kernel<<<NBLK, NTHR>>>(x, w_ih, b_ih, b_hh, w_fc, b_fc, (float*)d_out);
}